// round 1
// baseline (speedup 1.0000x reference)
#include <cuda_runtime.h>
#include <math.h>

// ---------------- problem constants ----------------
#define Bc     8
#define Tc     2048
#define VDIMc  1024
#define ADIMc  768
#define DMc    256
#define HIDc   1024
#define MROWS  (Bc * Tc)          // 16384
#define XDIM   (3 * DMc)          // 768

// ---------------- scratch (device globals; no allocation allowed) ----------------
__device__ float g_v   [MROWS * DMc];   // LN'd video projection
__device__ float g_a   [MROWS * DMc];   // LN'd audio projection
__device__ float g_actx[MROWS * DMc];   // windowed context
__device__ float g_x   [MROWS * XDIM];  // [an, vn, an*vn]
__device__ float g_part[MROWS * 8];     // per-column-block partial logits

// ---------------- block reduce (256 threads) ----------------
__device__ __forceinline__ float block_reduce_256(float val, float* sh) {
    int lane = threadIdx.x & 31, w = threadIdx.x >> 5;
#pragma unroll
    for (int o = 16; o > 0; o >>= 1) val += __shfl_down_sync(0xffffffffu, val, o);
    if (lane == 0) sh[w] = val;
    __syncthreads();
    if (w == 0) {
        float v2 = (lane < 8) ? sh[lane] : 0.f;
#pragma unroll
        for (int o = 4; o > 0; o >>= 1) v2 += __shfl_down_sync(0xffffffffu, v2, o);
        if (lane == 0) sh[0] = v2;
    }
    __syncthreads();
    float r = sh[0];
    __syncthreads();
    return r;
}

// ---------------- SGEMM: C[M,N] = A[M,K] @ B[K,N] + bias ----------------
// FUSE=false : store C (row-major)
// FUSE=true  : h = gelu(acc + bias); partial logit = sum_j h*W2[j] per row,
//              written per column-block to `part` (deterministic reduction later)
#define BMt 128
#define BNt 128
#define BKt 8
#define TMt 8
#define TNt 8

template <bool FUSE>
__global__ __launch_bounds__(256)
void sgemm_kernel(const float* __restrict__ A, const float* __restrict__ Bmat,
                  const float* __restrict__ bias, float* __restrict__ C,
                  int K, int N,
                  const float* __restrict__ W2, float* __restrict__ part)
{
    __shared__ float As[BKt][BMt];   // transposed A tile
    __shared__ float Bs[BKt][BNt];

    const int tid = threadIdx.x;
    const int bx = blockIdx.x, by = blockIdx.y;

    const int aRow = tid >> 1;            // 128 rows, 2 threads/row
    const int aCol = (tid & 1) * 4;       // float4 offset within BK=8
    const int bRow = tid >> 5;            // 8 rows
    const int bCol = (tid & 31) * 4;      // 32 * float4 = 128
    const int tr = tid >> 4;              // 0..15
    const int tc = tid & 15;              // 0..15

    const float* Ap = A + (size_t)(by * BMt + aRow) * K + aCol;
    const float* Bp = Bmat + (size_t)bRow * N + (size_t)bx * BNt + bCol;

    float acc[TMt][TNt];
#pragma unroll
    for (int i = 0; i < TMt; i++)
#pragma unroll
        for (int j = 0; j < TNt; j++) acc[i][j] = 0.f;

    for (int k0 = 0; k0 < K; k0 += BKt) {
        float4 av = *(const float4*)(Ap + k0);
        As[aCol + 0][aRow] = av.x;
        As[aCol + 1][aRow] = av.y;
        As[aCol + 2][aRow] = av.z;
        As[aCol + 3][aRow] = av.w;
        *(float4*)&Bs[bRow][bCol] = *(const float4*)(Bp + (size_t)k0 * N);
        __syncthreads();

#pragma unroll
        for (int k = 0; k < BKt; k++) {
            float ar[TMt], br[TNt];
            *(float4*)(ar)     = *(const float4*)&As[k][tr * TMt];
            *(float4*)(ar + 4) = *(const float4*)&As[k][tr * TMt + 4];
            *(float4*)(br)     = *(const float4*)&Bs[k][tc * TNt];
            *(float4*)(br + 4) = *(const float4*)&Bs[k][tc * TNt + 4];
#pragma unroll
            for (int i = 0; i < TMt; i++)
#pragma unroll
                for (int j = 0; j < TNt; j++)
                    acc[i][j] = fmaf(ar[i], br[j], acc[i][j]);
        }
        __syncthreads();
    }

    if (!FUSE) {
#pragma unroll
        for (int i = 0; i < TMt; i++) {
            const size_t row = (size_t)(by * BMt + tr * TMt + i);
            const int colb = bx * BNt + tc * TNt;
            float4 o0, o1;
            o0.x = acc[i][0] + bias[colb + 0];
            o0.y = acc[i][1] + bias[colb + 1];
            o0.z = acc[i][2] + bias[colb + 2];
            o0.w = acc[i][3] + bias[colb + 3];
            o1.x = acc[i][4] + bias[colb + 4];
            o1.y = acc[i][5] + bias[colb + 5];
            o1.z = acc[i][6] + bias[colb + 6];
            o1.w = acc[i][7] + bias[colb + 7];
            *(float4*)(C + row * N + colb)     = o0;
            *(float4*)(C + row * N + colb + 4) = o1;
        }
    } else {
        __shared__ float rowsum[BMt];
        for (int i = tid; i < BMt; i += 256) rowsum[i] = 0.f;
        __syncthreads();
        float p[TMt];
#pragma unroll
        for (int i = 0; i < TMt; i++) p[i] = 0.f;
#pragma unroll
        for (int i = 0; i < TMt; i++) {
#pragma unroll
            for (int j = 0; j < TNt; j++) {
                int col = bx * BNt + tc * TNt + j;
                float h = acc[i][j] + bias[col];
                h = 0.5f * h * (1.f + erff(h * 0.70710678118654752f)); // exact gelu
                p[i] += h * W2[col];
            }
        }
#pragma unroll
        for (int i = 0; i < TMt; i++) atomicAdd(&rowsum[tr * TMt + i], p[i]);
        __syncthreads();
        for (int i = tid; i < BMt; i += 256)
            part[(size_t)(by * BMt + i) * gridDim.x + bx] = rowsum[i];
    }
}

// ---------------- row LayerNorm over DM=256, in place ----------------
__global__ __launch_bounds__(256)
void ln_kernel(float* __restrict__ X)
{
    __shared__ float sh[8];
    const size_t row = blockIdx.x;
    float v = X[row * DMc + threadIdx.x];
    float mu = block_reduce_256(v, sh) * (1.f / DMc);
    float d = v - mu;
    float var = block_reduce_256(d * d, sh) * (1.f / DMc);
    X[row * DMc + threadIdx.x] = d * rsqrtf(var + 1e-5f);
}

// ---------------- fractional shift + causal 6-wide window average ----------------
// center = min(t + delta, t) = t (delta in (2,6)), so mask = tau in [max(0,t-5), t],
// uniformly weighted. a_shift[tau] = (1-alpha)*a[clip(tau-n)] + alpha*a[clip(tau-n+1)].
__global__ __launch_bounds__(256)
void shiftctx_kernel(const float* __restrict__ theta)
{
    const int t = blockIdx.x, b = blockIdx.y, d = threadIdx.x;
    float th = fminf(fmaxf(theta[0], -12.f), 12.f);
    float delta = 2.f + 4.f / (1.f + expf(-th));
    float dl = fminf(fmaxf(delta, 0.f), (float)(Tc - 1));
    float nf = floorf(dl);
    float alpha = dl - nf;
    int ni = (int)nf;

    const int lo = max(0, t - 5);
    const float* arow = g_a + (size_t)b * Tc * DMc;
    float sum = 0.f;
    for (int tau = lo; tau <= t; tau++) {
        int i0 = min(max(tau - ni, 0), Tc - 1);
        int i1 = min(i0 + 1, Tc - 1);
        sum += (1.f - alpha) * arow[(size_t)i0 * DMc + d]
             +        alpha  * arow[(size_t)i1 * DMc + d];
    }
    g_actx[((size_t)b * Tc + t) * DMc + d] = sum / (float)(t - lo + 1);
}

// ---------------- build x = [an, vn, an*vn] ----------------
__global__ __launch_bounds__(256)
void xbuild_kernel()
{
    __shared__ float sh[8];
    const size_t row = blockIdx.x;
    const int d = threadIdx.x;
    float vv = g_v[row * DMc + d];
    float aa = g_actx[row * DMc + d];
    float ssv = block_reduce_256(vv * vv, sh);
    float ssa = block_reduce_256(aa * aa, sh);
    float vn = vv / fmaxf(sqrtf(ssv), 1e-8f);
    float an = aa / fmaxf(sqrtf(ssa), 1e-8f);
    float* xr = g_x + row * XDIM;
    xr[d]           = an;
    xr[DMc + d]     = vn;
    xr[2 * DMc + d] = an * vn;
}

// ---------------- finalize: logits -> gate -> blend ----------------
__global__ __launch_bounds__(256)
void final_kernel(const float* __restrict__ b2, float* __restrict__ out)
{
    const size_t row = blockIdx.x;
    const int d = threadIdx.x;
    float l = b2[0];
#pragma unroll
    for (int p = 0; p < 8; p++) l += g_part[row * 8 + p];
    l = fminf(fmaxf(l, -12.f), 12.f);
    float g = 1.f / (1.f + expf(-l));
    g = fminf(fmaxf(g, 0.05f), 0.95f);
    size_t idx = row * DMc + d;
    out[idx] = g * g_actx[idx] + (1.f - g) * g_v[idx];
}

// ---------------- launch ----------------
extern "C" void kernel_launch(void* const* d_in, const int* in_sizes, int n_in,
                              void* d_out, int out_size)
{
    const float* video = (const float*)d_in[0];
    const float* audio = (const float*)d_in[1];
    const float* Wv    = (const float*)d_in[2];
    const float* bv    = (const float*)d_in[3];
    const float* Wa    = (const float*)d_in[4];
    const float* ba    = (const float*)d_in[5];
    const float* theta = (const float*)d_in[6];
    const float* W1    = (const float*)d_in[7];
    const float* b1    = (const float*)d_in[8];
    const float* W2    = (const float*)d_in[9];
    const float* b2    = (const float*)d_in[10];
    float* out = (float*)d_out;

    float *gv, *ga, *gx, *gpart;
    cudaGetSymbolAddress((void**)&gv,    g_v);
    cudaGetSymbolAddress((void**)&ga,    g_a);
    cudaGetSymbolAddress((void**)&gx,    g_x);
    cudaGetSymbolAddress((void**)&gpart, g_part);

    // 1) video projection -> g_v
    sgemm_kernel<false><<<dim3(DMc / BNt, MROWS / BMt), 256>>>(
        video, Wv, bv, gv, VDIMc, DMc, nullptr, nullptr);
    // 2) audio projection -> g_a
    sgemm_kernel<false><<<dim3(DMc / BNt, MROWS / BMt), 256>>>(
        audio, Wa, ba, ga, ADIMc, DMc, nullptr, nullptr);
    // 3) layernorms (in place)
    ln_kernel<<<MROWS, 256>>>(gv);
    ln_kernel<<<MROWS, 256>>>(ga);
    // 4) shift + window context -> g_actx
    shiftctx_kernel<<<dim3(Tc, Bc), 256>>>(theta);
    // 5) x = [an, vn, an*vn]
    xbuild_kernel<<<MROWS, 256>>>();
    // 6) gate MLP GEMM with fused gelu + W2 reduction -> g_part
    sgemm_kernel<true><<<dim3(HIDc / BNt, MROWS / BMt), 256>>>(
        gx, W1, b1, nullptr, XDIM, HIDc, W2, gpart);
    // 7) gate + blend -> out
    final_kernel<<<MROWS, 256>>>(b2, out);
}

// round 3
// speedup vs baseline: 1.5059x; 1.5059x over previous
#include <cuda_runtime.h>
#include <cuda_bf16.h>
#include <math.h>
#include <stdint.h>

// ---------------- problem constants ----------------
#define Bc     8
#define Tc     2048
#define VDIMc  1024
#define ADIMc  768
#define DMc    256
#define HIDc   1024
#define MROWS  (Bc * Tc)          // 16384
#define XDIM   (3 * DMc)          // 768
#define KV3    (3 * VDIMc)        // 3072
#define KA3    (3 * ADIMc)        // 2304
#define KX3    (3 * XDIM)         // 2304

// ---------------- scratch (device globals; no allocation allowed) ----------------
__device__ float g_v   [MROWS * DMc];
__device__ float g_a   [MROWS * DMc];
__device__ float g_actx[MROWS * DMc];
__device__ float g_part[MROWS * 8];

__device__ __nv_bfloat16 g_Av[(size_t)MROWS * KV3];  // [Ah|Ah|Al] video
__device__ __nv_bfloat16 g_Aa[(size_t)MROWS * KA3];  // audio
__device__ __nv_bfloat16 g_Ax[(size_t)MROWS * KX3];  // features
__device__ __nv_bfloat16 g_Bv[DMc  * KV3];           // WvT' [N,3K] = [Bh|Bl|Bh]
__device__ __nv_bfloat16 g_Ba[DMc  * KA3];
__device__ __nv_bfloat16 g_B1[HIDc * KX3];

// ---------------- helpers ----------------
__device__ __forceinline__ uint32_t smem_u32(const void* p) {
    uint32_t a;
    asm("{ .reg .u64 t; cvta.to.shared.u64 t, %1; cvt.u32.u64 %0, t; }" : "=r"(a) : "l"(p));
    return a;
}
__device__ __forceinline__ void split1(float x, __nv_bfloat16& h, __nv_bfloat16& l) {
    h = __float2bfloat16(x);
    l = __float2bfloat16(x - __bfloat162float(h));
}
__device__ __forceinline__ float gelu_exact(float h) {
    return 0.5f * h * (1.f + erff(h * 0.70710678118654752f));
}

#define LDSM4(rg, addr) \
    asm volatile("ldmatrix.sync.aligned.m8n8.x4.shared.b16 {%0,%1,%2,%3}, [%4];" \
        : "=r"((rg)[0]), "=r"((rg)[1]), "=r"((rg)[2]), "=r"((rg)[3]) : "r"(addr))

#define MMA16816(d, a, b) \
    asm volatile("mma.sync.aligned.m16n8k16.row.col.f32.bf16.bf16.f32 " \
        "{%0,%1,%2,%3}, {%4,%5,%6,%7}, {%8,%9}, {%0,%1,%2,%3};" \
        : "+f"((d)[0]), "+f"((d)[1]), "+f"((d)[2]), "+f"((d)[3]) \
        : "r"((a)[0]), "r"((a)[1]), "r"((a)[2]), "r"((a)[3]), "r"((b)[0]), "r"((b)[1]))

#define CP_ASYNC16(dst, src) \
    asm volatile("cp.async.cg.shared.global [%0], [%1], 16;" :: "r"(dst), "l"(src) : "memory")
#define CP_COMMIT() asm volatile("cp.async.commit_group;" ::: "memory")
#define CP_WAIT1()  asm volatile("cp.async.wait_group 1;" ::: "memory")

// smem tile: 128 rows x 64 bytes (32 bf16), XOR swizzle on 16B groups
__device__ __forceinline__ uint32_t sw_off(int r, int c16) {
    return (uint32_t)(((r << 6) + (c16 << 4)) ^ ((r & 3) << 4));
}

// ---------------- bf16 mma.sync GEMM: C[M,Ntot] = A'[M,K] @ B'[Ntot,K]^T ----------------
#define STAGES 3
#define TILEB  16384                       // A(8KB) + B(8KB) per stage
static constexpr int SM_EPI   = STAGES * TILEB;    // 49152
static constexpr int GSM_TOTAL = SM_EPI + 1536;    // +bias/w2/rowsum

template <bool FUSE>
__global__ void __launch_bounds__(256, 1)
mma_gemm(const __nv_bfloat16* __restrict__ A, const __nv_bfloat16* __restrict__ Bm,
         const float* __restrict__ bias, const float* __restrict__ W2,
         float* __restrict__ out, int K, int Ntot)
{
    extern __shared__ char smem[];
    const uint32_t sbase = smem_u32(smem);
    const int tid  = threadIdx.x;
    const int lane = tid & 31, warp = tid >> 5;
    const int wm = warp >> 2, wn = warp & 3;          // 2 x 4 warp grid (64m x 32n)
    const int bx = blockIdx.x, by = blockIdx.y;

    float* sBias = (float*)(smem + SM_EPI);
    float* sW2   = (float*)(smem + SM_EPI + 512);
    float* sRow  = (float*)(smem + SM_EPI + 1024);
    if (tid < 128) {
        sBias[tid] = bias[bx * 128 + tid];
        if (FUSE) { sW2[tid] = W2[bx * 128 + tid]; sRow[tid] = 0.f; }
    }

    const __nv_bfloat16* Ab = A  + (size_t)(by * 128) * K;
    const __nv_bfloat16* Bb = Bm + (size_t)(bx * 128) * K;

    // per-thread cp.async chunks: tile = 512 x 16B chunks; this thread: chunk tid, tid+256
    const int cr = tid >> 2, cc = tid & 3;

    float acc[4][4][4];
#pragma unroll
    for (int i = 0; i < 4; i++)
#pragma unroll
        for (int j = 0; j < 4; j++)
#pragma unroll
            for (int q = 0; q < 4; q++) acc[i][j][q] = 0.f;

    const int nt = K >> 5;   // K / 32

    // ---- pipeline load ----
    auto load_tile = [&](int stage, int kt) {
        const uint32_t sA = sbase + stage * TILEB;
        const uint32_t sB = sA + 8192;
        const __nv_bfloat16* a0 = Ab + (size_t)cr * K + kt * 32 + cc * 8;
        const __nv_bfloat16* b0 = Bb + (size_t)cr * K + kt * 32 + cc * 8;
        CP_ASYNC16(sA + sw_off(cr,      cc), a0);
        CP_ASYNC16(sA + sw_off(cr + 64, cc), a0 + (size_t)64 * K);
        CP_ASYNC16(sB + sw_off(cr,      cc), b0);
        CP_ASYNC16(sB + sw_off(cr + 64, cc), b0 + (size_t)64 * K);
    };

    load_tile(0, 0); CP_COMMIT();
    load_tile(1, 1); CP_COMMIT();

    // precomputed fragment row/col components
    const int arow = wm * 64 + (lane & 15);       // + mt*16
    const int acsel = lane >> 4;                  // +0/1 16B group
    const int brow = wn * 32 + (lane & 7) + ((lane >> 4) << 3);  // + nt16*16
    const int bcsel = (lane >> 3) & 1;

    for (int kt = 0; kt < nt; kt++) {
        CP_WAIT1();
        __syncthreads();

        const int nk = kt + 2;
        if (nk < nt) load_tile(nk % STAGES, nk);
        CP_COMMIT();

        const uint32_t sA = sbase + (kt % STAGES) * TILEB;
        const uint32_t sB = sA + 8192;
#pragma unroll
        for (int ks = 0; ks < 2; ks++) {
            uint32_t afr[4][4], bfr[2][4];
#pragma unroll
            for (int mt = 0; mt < 4; mt++)
                LDSM4(afr[mt], sA + sw_off(arow + mt * 16, ks * 2 + acsel));
#pragma unroll
            for (int nb = 0; nb < 2; nb++)
                LDSM4(bfr[nb], sB + sw_off(brow + nb * 16, ks * 2 + bcsel));
#pragma unroll
            for (int mt = 0; mt < 4; mt++) {
#pragma unroll
                for (int n8 = 0; n8 < 4; n8++) {
                    uint32_t bb[2] = { bfr[n8 >> 1][(n8 & 1) * 2], bfr[n8 >> 1][(n8 & 1) * 2 + 1] };
                    MMA16816(acc[mt][n8], afr[mt], bb);
                }
            }
        }
        __syncthreads();
    }

    // ---- epilogue ----
    if (!FUSE) {
#pragma unroll
        for (int mt = 0; mt < 4; mt++) {
            const int row = by * 128 + wm * 64 + mt * 16 + (lane >> 2);
#pragma unroll
            for (int n8 = 0; n8 < 4; n8++) {
                const int lc  = wn * 32 + n8 * 8 + (lane & 3) * 2;
                const int col = bx * 128 + lc;
                float2 v0 = { acc[mt][n8][0] + sBias[lc], acc[mt][n8][1] + sBias[lc + 1] };
                float2 v1 = { acc[mt][n8][2] + sBias[lc], acc[mt][n8][3] + sBias[lc + 1] };
                *reinterpret_cast<float2*>(out + (size_t)row * Ntot + col)       = v0;
                *reinterpret_cast<float2*>(out + (size_t)(row + 8) * Ntot + col) = v1;
            }
        }
    } else {
#pragma unroll
        for (int mt = 0; mt < 4; mt++) {
            float pA = 0.f, pB = 0.f;
#pragma unroll
            for (int n8 = 0; n8 < 4; n8++) {
                const int lc = wn * 32 + n8 * 8 + (lane & 3) * 2;
                pA += gelu_exact(acc[mt][n8][0] + sBias[lc])     * sW2[lc];
                pA += gelu_exact(acc[mt][n8][1] + sBias[lc + 1]) * sW2[lc + 1];
                pB += gelu_exact(acc[mt][n8][2] + sBias[lc])     * sW2[lc];
                pB += gelu_exact(acc[mt][n8][3] + sBias[lc + 1]) * sW2[lc + 1];
            }
            pA += __shfl_xor_sync(0xffffffffu, pA, 1);
            pA += __shfl_xor_sync(0xffffffffu, pA, 2);
            pB += __shfl_xor_sync(0xffffffffu, pB, 1);
            pB += __shfl_xor_sync(0xffffffffu, pB, 2);
            if ((lane & 3) == 0) {
                atomicAdd(&sRow[wm * 64 + mt * 16 + (lane >> 2)],     pA);
                atomicAdd(&sRow[wm * 64 + mt * 16 + (lane >> 2) + 8], pB);
            }
        }
        __syncthreads();
        if (tid < 128)
            out[(size_t)(by * 128 + tid) * gridDim.x + bx] = sRow[tid];
    }
}

// ---------------- activation split: X[M,Kd] f32 -> [hi|hi|lo] bf16 [M,3Kd] ----------------
__global__ __launch_bounds__(256)
void split_act(const float4* __restrict__ X, __nv_bfloat16* __restrict__ dst, int ncols4)
{
    int i = blockIdx.x * 256 + threadIdx.x;
    int total = MROWS * ncols4;
    if (i >= total) return;
    int row = i / ncols4, c4 = i - row * ncols4;
    float4 x = X[i];
    __nv_bfloat16 h0, h1, h2, h3, l0, l1, l2, l3;
    split1(x.x, h0, l0); split1(x.y, h1, l1); split1(x.z, h2, l2); split1(x.w, h3, l3);
    ushort4 hv = { __bfloat16_as_ushort(h0), __bfloat16_as_ushort(h1),
                   __bfloat16_as_ushort(h2), __bfloat16_as_ushort(h3) };
    ushort4 lv = { __bfloat16_as_ushort(l0), __bfloat16_as_ushort(l1),
                   __bfloat16_as_ushort(l2), __bfloat16_as_ushort(l3) };
    ushort4* p = reinterpret_cast<ushort4*>(dst + (size_t)row * (3 * ncols4 * 4));
    p[c4] = hv;
    p[ncols4 + c4] = hv;
    p[2 * ncols4 + c4] = lv;
}

// ---------------- weight transpose+split: W[K,N] -> B'[N,3K] = [Bh|Bl|Bh] ----------------
__global__ __launch_bounds__(256)
void wsplit(const float* __restrict__ W, __nv_bfloat16* __restrict__ dst, int K, int N)
{
    int idx = blockIdx.x * 256 + threadIdx.x;
    if (idx >= K * N) return;
    int k = idx / N, n = idx - k * N;
    __nv_bfloat16 h, l;
    split1(W[idx], h, l);
    __nv_bfloat16* p = dst + (size_t)n * 3 * K;
    p[k] = h; p[K + k] = l; p[2 * K + k] = h;
}

// ---------------- block reduce ----------------
__device__ __forceinline__ float block_reduce_256(float val, float* sh) {
    int lane = threadIdx.x & 31, w = threadIdx.x >> 5;
#pragma unroll
    for (int o = 16; o > 0; o >>= 1) val += __shfl_down_sync(0xffffffffu, val, o);
    if (lane == 0) sh[w] = val;
    __syncthreads();
    if (w == 0) {
        float v2 = (lane < 8) ? sh[lane] : 0.f;
#pragma unroll
        for (int o = 4; o > 0; o >>= 1) v2 += __shfl_down_sync(0xffffffffu, v2, o);
        if (lane == 0) sh[0] = v2;
    }
    __syncthreads();
    float r = sh[0];
    __syncthreads();
    return r;
}

// ---------------- LayerNorm (in place, DM=256) ----------------
__global__ __launch_bounds__(256)
void ln_kernel(float* __restrict__ X)
{
    __shared__ float sh[8];
    const size_t row = blockIdx.x;
    float v = X[row * DMc + threadIdx.x];
    float mu = block_reduce_256(v, sh) * (1.f / DMc);
    float d = v - mu;
    float var = block_reduce_256(d * d, sh) * (1.f / DMc);
    X[row * DMc + threadIdx.x] = d * rsqrtf(var + 1e-5f);
}

// ---------------- fractional shift + causal 6-wide window average ----------------
__global__ __launch_bounds__(256)
void shiftctx_kernel(const float* __restrict__ theta)
{
    const int t = blockIdx.x, b = blockIdx.y, d = threadIdx.x;
    float th = fminf(fmaxf(theta[0], -12.f), 12.f);
    float delta = 2.f + 4.f / (1.f + expf(-th));
    float dl = fminf(fmaxf(delta, 0.f), (float)(Tc - 1));
    float nf = floorf(dl);
    float alpha = dl - nf;
    int ni = (int)nf;

    const int lo = max(0, t - 5);
    const float* arow = g_a + (size_t)b * Tc * DMc;
    float sum = 0.f;
    for (int tau = lo; tau <= t; tau++) {
        int i0 = min(max(tau - ni, 0), Tc - 1);
        int i1 = min(i0 + 1, Tc - 1);
        sum += (1.f - alpha) * arow[(size_t)i0 * DMc + d]
             +        alpha  * arow[(size_t)i1 * DMc + d];
    }
    g_actx[((size_t)b * Tc + t) * DMc + d] = sum / (float)(t - lo + 1);
}

// ---------------- build x features -> g_Ax [hi|hi|lo] ----------------
__global__ __launch_bounds__(256)
void xbuild_kernel()
{
    __shared__ float sh[8];
    const size_t row = blockIdx.x;
    const int d = threadIdx.x;
    float vv = g_v[row * DMc + d];
    float aa = g_actx[row * DMc + d];
    float ssv = block_reduce_256(vv * vv, sh);
    float ssa = block_reduce_256(aa * aa, sh);
    float vn = vv / fmaxf(sqrtf(ssv), 1e-8f);
    float an = aa / fmaxf(sqrtf(ssa), 1e-8f);
    __nv_bfloat16 h, l;
    __nv_bfloat16* p = g_Ax + row * (size_t)KX3;
    split1(an, h, l);
    p[d] = h; p[XDIM + d] = h; p[2 * XDIM + d] = l;
    split1(vn, h, l);
    p[DMc + d] = h; p[XDIM + DMc + d] = h; p[2 * XDIM + DMc + d] = l;
    split1(an * vn, h, l);
    p[2 * DMc + d] = h; p[XDIM + 2 * DMc + d] = h; p[2 * XDIM + 2 * DMc + d] = l;
}

// ---------------- finalize ----------------
__global__ __launch_bounds__(256)
void final_kernel(const float* __restrict__ b2, float* __restrict__ out)
{
    const size_t row = blockIdx.x;
    const int d = threadIdx.x;
    float l = b2[0];
#pragma unroll
    for (int p = 0; p < 8; p++) l += g_part[row * 8 + p];
    l = fminf(fmaxf(l, -12.f), 12.f);
    float g = 1.f / (1.f + expf(-l));
    g = fminf(fmaxf(g, 0.05f), 0.95f);
    size_t idx = row * DMc + d;
    out[idx] = g * g_actx[idx] + (1.f - g) * g_v[idx];
}

// ---------------- launch ----------------
extern "C" void kernel_launch(void* const* d_in, const int* in_sizes, int n_in,
                              void* d_out, int out_size)
{
    const float* video = (const float*)d_in[0];
    const float* audio = (const float*)d_in[1];
    const float* Wv    = (const float*)d_in[2];
    const float* bv    = (const float*)d_in[3];
    const float* Wa    = (const float*)d_in[4];
    const float* ba    = (const float*)d_in[5];
    const float* theta = (const float*)d_in[6];
    const float* W1    = (const float*)d_in[7];
    const float* b1    = (const float*)d_in[8];
    const float* W2    = (const float*)d_in[9];
    const float* b2    = (const float*)d_in[10];
    float* out = (float*)d_out;

    float *gv, *ga, *gpart;
    __nv_bfloat16 *av, *aa, *ax, *bvw, *baw, *b1w;
    cudaGetSymbolAddress((void**)&gv, g_v);
    cudaGetSymbolAddress((void**)&ga, g_a);
    cudaGetSymbolAddress((void**)&gpart, g_part);
    cudaGetSymbolAddress((void**)&av, g_Av);
    cudaGetSymbolAddress((void**)&aa, g_Aa);
    cudaGetSymbolAddress((void**)&ax, g_Ax);
    cudaGetSymbolAddress((void**)&bvw, g_Bv);
    cudaGetSymbolAddress((void**)&baw, g_Ba);
    cudaGetSymbolAddress((void**)&b1w, g_B1);

    cudaFuncSetAttribute(mma_gemm<false>, cudaFuncAttributeMaxDynamicSharedMemorySize, GSM_TOTAL);
    cudaFuncSetAttribute(mma_gemm<true>,  cudaFuncAttributeMaxDynamicSharedMemorySize, GSM_TOTAL);

    // splits
    split_act<<<(MROWS * (VDIMc / 4) + 255) / 256, 256>>>((const float4*)video, av, VDIMc / 4);
    split_act<<<(MROWS * (ADIMc / 4) + 255) / 256, 256>>>((const float4*)audio, aa, ADIMc / 4);
    wsplit<<<(VDIMc * DMc + 255) / 256, 256>>>(Wv, bvw, VDIMc, DMc);
    wsplit<<<(ADIMc * DMc + 255) / 256, 256>>>(Wa, baw, ADIMc, DMc);
    wsplit<<<(XDIM * HIDc + 255) / 256, 256>>>(W1, b1w, XDIM, HIDc);

    // projections
    mma_gemm<false><<<dim3(DMc / 128, MROWS / 128), 256, GSM_TOTAL>>>(
        av, bvw, bv, nullptr, gv, KV3, DMc);
    mma_gemm<false><<<dim3(DMc / 128, MROWS / 128), 256, GSM_TOTAL>>>(
        aa, baw, ba, nullptr, ga, KA3, DMc);

    ln_kernel<<<MROWS, 256>>>(gv);
    ln_kernel<<<MROWS, 256>>>(ga);
    shiftctx_kernel<<<dim3(Tc, Bc), 256>>>(theta);
    xbuild_kernel<<<MROWS, 256>>>();

    // gate MLP with fused gelu + W2 reduction
    mma_gemm<true><<<dim3(HIDc / 128, MROWS / 128), 256, GSM_TOTAL>>>(
        ax, b1w, b1, W2, gpart, KX3, HIDc);

    final_kernel<<<MROWS, 256>>>(b2, out);
}

// round 5
// speedup vs baseline: 1.8635x; 1.2375x over previous
#include <cuda_runtime.h>
#include <cuda_bf16.h>
#include <math.h>
#include <stdint.h>

// ---------------- problem constants ----------------
#define Bc     8
#define Tc     2048
#define VDIMc  1024
#define ADIMc  768
#define DMc    256
#define HIDc   1024
#define MROWS  (Bc * Tc)          // 16384
#define XDIM   (3 * DMc)          // 768

// ---------------- scratch (device globals; no allocation allowed) ----------------
__device__ float g_v   [MROWS * DMc];
__device__ float g_a   [MROWS * DMc];
__device__ float g_actx[MROWS * DMc];
__device__ float g_part[MROWS * 8];

__device__ __nv_bfloat16 g_Vhi[(size_t)MROWS * VDIMc];
__device__ __nv_bfloat16 g_Vlo[(size_t)MROWS * VDIMc];
__device__ __nv_bfloat16 g_Ahi[(size_t)MROWS * ADIMc];
__device__ __nv_bfloat16 g_Alo[(size_t)MROWS * ADIMc];
__device__ __nv_bfloat16 g_Xhi[(size_t)MROWS * XDIM];
__device__ __nv_bfloat16 g_Xlo[(size_t)MROWS * XDIM];
__device__ __nv_bfloat16 g_Bv[DMc  * 3 * VDIMc];   // [Bh|Bl|Bh] per row, [N,3K]
__device__ __nv_bfloat16 g_Ba[DMc  * 3 * ADIMc];
__device__ __nv_bfloat16 g_B1[HIDc * 3 * XDIM];

// ---------------- helpers ----------------
__device__ __forceinline__ uint32_t smem_u32(const void* p) {
    uint32_t a;
    asm("{ .reg .u64 t; cvta.to.shared.u64 t, %1; cvt.u32.u64 %0, t; }" : "=r"(a) : "l"(p));
    return a;
}
__device__ __forceinline__ void split1(float x, __nv_bfloat16& h, __nv_bfloat16& l) {
    h = __float2bfloat16(x);
    l = __float2bfloat16(x - __bfloat162float(h));
}
__device__ __forceinline__ float gelu_exact(float h) {
    return 0.5f * h * (1.f + erff(h * 0.70710678118654752f));
}

#define LDSM4(rg, addr) \
    asm volatile("ldmatrix.sync.aligned.m8n8.x4.shared.b16 {%0,%1,%2,%3}, [%4];" \
        : "=r"((rg)[0]), "=r"((rg)[1]), "=r"((rg)[2]), "=r"((rg)[3]) : "r"(addr))

#define MMA16816(d, a, b) \
    asm volatile("mma.sync.aligned.m16n8k16.row.col.f32.bf16.bf16.f32 " \
        "{%0,%1,%2,%3}, {%4,%5,%6,%7}, {%8,%9}, {%0,%1,%2,%3};" \
        : "+f"((d)[0]), "+f"((d)[1]), "+f"((d)[2]), "+f"((d)[3]) \
        : "r"((a)[0]), "r"((a)[1]), "r"((a)[2]), "r"((a)[3]), "r"((b)[0]), "r"((b)[1]))

#define CP_ASYNC16(dst, src) \
    asm volatile("cp.async.cg.shared.global [%0], [%1], 16;" :: "r"(dst), "l"(src) : "memory")
#define CP_COMMIT() asm volatile("cp.async.commit_group;" ::: "memory")
#define CP_WAIT1()  asm volatile("cp.async.wait_group 1;" ::: "memory")

// smem tile: 128 rows x 64 bytes (32 bf16), XOR swizzle on 16B groups
__device__ __forceinline__ uint32_t sw_off(int r, int c16) {
    return (uint32_t)(((r << 6) + (c16 << 4)) ^ ((r & 3) << 4));
}

// ---------------- bf16 mma.sync GEMM ----------------
// C[M,Ntot] = [Ah|Ah|Al] @ [Bh|Bl|Bh]^T ; A hi/lo separate [M,K], B packed [Ntot,3K]
#define STAGES 3
#define TILEB  16384
static constexpr int SM_EPI    = STAGES * TILEB;     // 49152
static constexpr int GSM_TOTAL = SM_EPI + 1536;

template <bool FUSE>
__global__ void __launch_bounds__(256, 2)
mma_gemm(const __nv_bfloat16* __restrict__ Ahi, const __nv_bfloat16* __restrict__ Alo,
         const __nv_bfloat16* __restrict__ Bm,
         const float* __restrict__ bias, const float* __restrict__ W2,
         float* __restrict__ out, int K, int Ntot)
{
    extern __shared__ char smem[];
    const uint32_t sbase = smem_u32(smem);
    const int tid  = threadIdx.x;
    const int lane = tid & 31, warp = tid >> 5;
    const int wm = warp >> 2, wn = warp & 3;          // 2 x 4 warp grid (64m x 32n)
    const int bx = blockIdx.x, by = blockIdx.y;

    float* sBias = (float*)(smem + SM_EPI);
    float* sW2   = (float*)(smem + SM_EPI + 512);
    float* sRow  = (float*)(smem + SM_EPI + 1024);
    if (tid < 128) {
        sBias[tid] = bias[bx * 128 + tid];
        if (FUSE) { sW2[tid] = W2[bx * 128 + tid]; sRow[tid] = 0.f; }
    }

    const int ntK = K >> 5;           // chunks per region
    const int nt  = 3 * ntK;
    const int K3  = 3 * K;

    // per-thread cp.async chunk coords
    const int cr = tid >> 2, cc = tid & 3;

    const __nv_bfloat16* Ah_b = Ahi + (size_t)(by * 128) * K + (size_t)cr * K + cc * 8;
    const __nv_bfloat16* Al_b = Alo + (size_t)(by * 128) * K + (size_t)cr * K + cc * 8;
    const __nv_bfloat16* Bb   = Bm  + (size_t)(bx * 128) * K3 + (size_t)cr * K3 + cc * 8;

    float acc[4][4][4];
#pragma unroll
    for (int i = 0; i < 4; i++)
#pragma unroll
        for (int j = 0; j < 4; j++)
#pragma unroll
            for (int q = 0; q < 4; q++) acc[i][j][q] = 0.f;

    auto load_tile = [&](int stage, int kt) {
        const uint32_t sA = sbase + stage * TILEB;
        const uint32_t sB = sA + 8192;
        int klocal = kt;
        const __nv_bfloat16* Ar;
        if (kt >= 2 * ntK)      { Ar = Al_b; klocal = kt - 2 * ntK; }
        else if (kt >= ntK)     { Ar = Ah_b; klocal = kt - ntK; }
        else                    { Ar = Ah_b; }
        const __nv_bfloat16* a0 = Ar + klocal * 32;
        const __nv_bfloat16* b0 = Bb + kt * 32;
        CP_ASYNC16(sA + sw_off(cr,      cc), a0);
        CP_ASYNC16(sA + sw_off(cr + 64, cc), a0 + (size_t)64 * K);
        CP_ASYNC16(sB + sw_off(cr,      cc), b0);
        CP_ASYNC16(sB + sw_off(cr + 64, cc), b0 + (size_t)64 * K3);
    };

    load_tile(0, 0); CP_COMMIT();
    load_tile(1, 1); CP_COMMIT();

    const int arow  = wm * 64 + (lane & 15);
    const int acsel = lane >> 4;
    const int brow  = wn * 32 + (lane & 7) + ((lane >> 4) << 3);
    const int bcsel = (lane >> 3) & 1;

    for (int kt = 0; kt < nt; kt++) {
        CP_WAIT1();
        __syncthreads();

        const int nk = kt + 2;
        if (nk < nt) load_tile(nk % STAGES, nk);
        CP_COMMIT();

        const uint32_t sA = sbase + (kt % STAGES) * TILEB;
        const uint32_t sB = sA + 8192;
#pragma unroll
        for (int ks = 0; ks < 2; ks++) {
            uint32_t afr[4][4], bfr[2][4];
#pragma unroll
            for (int mt = 0; mt < 4; mt++)
                LDSM4(afr[mt], sA + sw_off(arow + mt * 16, ks * 2 + acsel));
#pragma unroll
            for (int nb = 0; nb < 2; nb++)
                LDSM4(bfr[nb], sB + sw_off(brow + nb * 16, ks * 2 + bcsel));
#pragma unroll
            for (int mt = 0; mt < 4; mt++) {
#pragma unroll
                for (int n8 = 0; n8 < 4; n8++) {
                    uint32_t bb[2] = { bfr[n8 >> 1][(n8 & 1) * 2], bfr[n8 >> 1][(n8 & 1) * 2 + 1] };
                    MMA16816(acc[mt][n8], afr[mt], bb);
                }
            }
        }
        // no trailing sync: next iteration's leading sync protects the stage
    }

    // ---- epilogue ----
    if (!FUSE) {
#pragma unroll
        for (int mt = 0; mt < 4; mt++) {
            const int row = by * 128 + wm * 64 + mt * 16 + (lane >> 2);
#pragma unroll
            for (int n8 = 0; n8 < 4; n8++) {
                const int lc  = wn * 32 + n8 * 8 + (lane & 3) * 2;
                const int col = bx * 128 + lc;
                float2 v0 = { acc[mt][n8][0] + sBias[lc], acc[mt][n8][1] + sBias[lc + 1] };
                float2 v1 = { acc[mt][n8][2] + sBias[lc], acc[mt][n8][3] + sBias[lc + 1] };
                *reinterpret_cast<float2*>(out + (size_t)row * Ntot + col)       = v0;
                *reinterpret_cast<float2*>(out + (size_t)(row + 8) * Ntot + col) = v1;
            }
        }
    } else {
#pragma unroll
        for (int mt = 0; mt < 4; mt++) {
            float pA = 0.f, pB = 0.f;
#pragma unroll
            for (int n8 = 0; n8 < 4; n8++) {
                const int lc = wn * 32 + n8 * 8 + (lane & 3) * 2;
                pA += gelu_exact(acc[mt][n8][0] + sBias[lc])     * sW2[lc];
                pA += gelu_exact(acc[mt][n8][1] + sBias[lc + 1]) * sW2[lc + 1];
                pB += gelu_exact(acc[mt][n8][2] + sBias[lc])     * sW2[lc];
                pB += gelu_exact(acc[mt][n8][3] + sBias[lc + 1]) * sW2[lc + 1];
            }
            pA += __shfl_xor_sync(0xffffffffu, pA, 1);
            pA += __shfl_xor_sync(0xffffffffu, pA, 2);
            pB += __shfl_xor_sync(0xffffffffu, pB, 1);
            pB += __shfl_xor_sync(0xffffffffu, pB, 2);
            if ((lane & 3) == 0) {
                atomicAdd(&sRow[wm * 64 + mt * 16 + (lane >> 2)],     pA);
                atomicAdd(&sRow[wm * 64 + mt * 16 + (lane >> 2) + 8], pB);
            }
        }
        __syncthreads();
        if (tid < 128)
            out[(size_t)(by * 128 + tid) * gridDim.x + bx] = sRow[tid];
    }
}

// ---------------- activation split: f32 -> bf16 hi + lo (separate buffers) ----------------
__global__ __launch_bounds__(256)
void split_act(const float4* __restrict__ X, __nv_bfloat16* __restrict__ hi,
               __nv_bfloat16* __restrict__ lo, int n4)
{
    int i = blockIdx.x * 256 + threadIdx.x;
    if (i >= n4) return;
    float4 x = X[i];
    __nv_bfloat16 h0, h1, h2, h3, l0, l1, l2, l3;
    split1(x.x, h0, l0); split1(x.y, h1, l1); split1(x.z, h2, l2); split1(x.w, h3, l3);
    ushort4 hv = { __bfloat16_as_ushort(h0), __bfloat16_as_ushort(h1),
                   __bfloat16_as_ushort(h2), __bfloat16_as_ushort(h3) };
    ushort4 lv = { __bfloat16_as_ushort(l0), __bfloat16_as_ushort(l1),
                   __bfloat16_as_ushort(l2), __bfloat16_as_ushort(l3) };
    *reinterpret_cast<ushort4*>(hi + 4 * (size_t)i) = hv;
    *reinterpret_cast<ushort4*>(lo + 4 * (size_t)i) = lv;
}

// ---------------- tiled weight transpose+split: W[K,N] -> [N,3K]=[Bh|Bl|Bh] ----------------
__global__ __launch_bounds__(256)
void wsplit(const float* __restrict__ W, __nv_bfloat16* __restrict__ dst, int K, int N)
{
    __shared__ float tile[32][33];
    const int k0 = blockIdx.x * 32, n0 = blockIdx.y * 32;
    const int tx = threadIdx.x & 31, ty8 = threadIdx.x >> 5;   // 32 x 8
#pragma unroll
    for (int i = 0; i < 4; i++) {
        int ty = ty8 + i * 8;
        tile[ty][tx] = W[(size_t)(k0 + ty) * N + n0 + tx];
    }
    __syncthreads();
#pragma unroll
    for (int i = 0; i < 4; i++) {
        int ny = ty8 + i * 8;
        float x = tile[tx][ny];                 // k = k0+tx, n = n0+ny
        __nv_bfloat16 h, l;
        split1(x, h, l);
        __nv_bfloat16* p = dst + (size_t)(n0 + ny) * 3 * K;
        p[k0 + tx]         = h;
        p[K + k0 + tx]     = l;
        p[2 * K + k0 + tx] = h;
    }
}

// ---------------- block reduce ----------------
__device__ __forceinline__ float block_reduce_256(float val, float* sh) {
    int lane = threadIdx.x & 31, w = threadIdx.x >> 5;
#pragma unroll
    for (int o = 16; o > 0; o >>= 1) val += __shfl_down_sync(0xffffffffu, val, o);
    if (lane == 0) sh[w] = val;
    __syncthreads();
    if (w == 0) {
        float v2 = (lane < 8) ? sh[lane] : 0.f;
#pragma unroll
        for (int o = 4; o > 0; o >>= 1) v2 += __shfl_down_sync(0xffffffffu, v2, o);
        if (lane == 0) sh[0] = v2;
    }
    __syncthreads();
    float r = sh[0];
    __syncthreads();
    return r;
}

// ---------------- LayerNorm (in place, DM=256) ----------------
__global__ __launch_bounds__(256)
void ln_kernel(float* __restrict__ X)
{
    __shared__ float sh[8];
    const size_t row = blockIdx.x;
    float v = X[row * DMc + threadIdx.x];
    float mu = block_reduce_256(v, sh) * (1.f / DMc);
    float d = v - mu;
    float var = block_reduce_256(d * d, sh) * (1.f / DMc);
    X[row * DMc + threadIdx.x] = d * rsqrtf(var + 1e-5f);
}

// ---------------- fractional shift + causal 6-wide window average ----------------
__global__ __launch_bounds__(256)
void shiftctx_kernel(const float* __restrict__ theta)
{
    const int t = blockIdx.x, b = blockIdx.y, d = threadIdx.x;
    float th = fminf(fmaxf(theta[0], -12.f), 12.f);
    float delta = 2.f + 4.f / (1.f + expf(-th));
    float dl = fminf(fmaxf(delta, 0.f), (float)(Tc - 1));
    float nf = floorf(dl);
    float alpha = dl - nf;
    int ni = (int)nf;

    const int lo = max(0, t - 5);
    const float* arow = g_a + (size_t)b * Tc * DMc;
    float sum = 0.f;
    for (int tau = lo; tau <= t; tau++) {
        int i0 = min(max(tau - ni, 0), Tc - 1);
        int i1 = min(i0 + 1, Tc - 1);
        sum += (1.f - alpha) * arow[(size_t)i0 * DMc + d]
             +        alpha  * arow[(size_t)i1 * DMc + d];
    }
    g_actx[((size_t)b * Tc + t) * DMc + d] = sum / (float)(t - lo + 1);
}

// ---------------- build x features -> Xhi/Xlo ----------------
__global__ __launch_bounds__(256)
void xbuild_kernel()
{
    __shared__ float sh[8];
    const size_t row = blockIdx.x;
    const int d = threadIdx.x;
    float vv = g_v[row * DMc + d];
    float aa = g_actx[row * DMc + d];
    float ssv = block_reduce_256(vv * vv, sh);
    float ssa = block_reduce_256(aa * aa, sh);
    float vn = vv / fmaxf(sqrtf(ssv), 1e-8f);
    float an = aa / fmaxf(sqrtf(ssa), 1e-8f);
    __nv_bfloat16 h, l;
    size_t base = row * XDIM;
    split1(an,      h, l); g_Xhi[base + d]           = h; g_Xlo[base + d]           = l;
    split1(vn,      h, l); g_Xhi[base + DMc + d]     = h; g_Xlo[base + DMc + d]     = l;
    split1(an * vn, h, l); g_Xhi[base + 2 * DMc + d] = h; g_Xlo[base + 2 * DMc + d] = l;
}

// ---------------- finalize ----------------
__global__ __launch_bounds__(256)
void final_kernel(const float* __restrict__ b2, float* __restrict__ out)
{
    const size_t row = blockIdx.x;
    const int d = threadIdx.x;
    float l = b2[0];
#pragma unroll
    for (int p = 0; p < 8; p++) l += g_part[row * 8 + p];
    l = fminf(fmaxf(l, -12.f), 12.f);
    float g = 1.f / (1.f + expf(-l));
    g = fminf(fmaxf(g, 0.05f), 0.95f);
    size_t idx = row * DMc + d;
    out[idx] = g * g_actx[idx] + (1.f - g) * g_v[idx];
}

// ---------------- launch ----------------
extern "C" void kernel_launch(void* const* d_in, const int* in_sizes, int n_in,
                              void* d_out, int out_size)
{
    const float* video = (const float*)d_in[0];
    const float* audio = (const float*)d_in[1];
    const float* Wv    = (const float*)d_in[2];
    const float* bv    = (const float*)d_in[3];
    const float* Wa    = (const float*)d_in[4];
    const float* ba    = (const float*)d_in[5];
    const float* theta = (const float*)d_in[6];
    const float* W1    = (const float*)d_in[7];
    const float* b1    = (const float*)d_in[8];
    const float* W2    = (const float*)d_in[9];
    const float* b2    = (const float*)d_in[10];
    float* out = (float*)d_out;

    float *gv, *ga, *gpart;
    __nv_bfloat16 *vh, *vl, *ah, *al, *xh, *xl, *bvw, *baw, *b1w;
    cudaGetSymbolAddress((void**)&gv, g_v);
    cudaGetSymbolAddress((void**)&ga, g_a);
    cudaGetSymbolAddress((void**)&gpart, g_part);
    cudaGetSymbolAddress((void**)&vh, g_Vhi); cudaGetSymbolAddress((void**)&vl, g_Vlo);
    cudaGetSymbolAddress((void**)&ah, g_Ahi); cudaGetSymbolAddress((void**)&al, g_Alo);
    cudaGetSymbolAddress((void**)&xh, g_Xhi); cudaGetSymbolAddress((void**)&xl, g_Xlo);
    cudaGetSymbolAddress((void**)&bvw, g_Bv);
    cudaGetSymbolAddress((void**)&baw, g_Ba);
    cudaGetSymbolAddress((void**)&b1w, g_B1);

    cudaFuncSetAttribute(mma_gemm<false>, cudaFuncAttributeMaxDynamicSharedMemorySize, GSM_TOTAL);
    cudaFuncSetAttribute(mma_gemm<true>,  cudaFuncAttributeMaxDynamicSharedMemorySize, GSM_TOTAL);

    // splits
    split_act<<<(MROWS * (VDIMc / 4) + 255) / 256, 256>>>((const float4*)video, vh, vl, MROWS * VDIMc / 4);
    split_act<<<(MROWS * (ADIMc / 4) + 255) / 256, 256>>>((const float4*)audio, ah, al, MROWS * ADIMc / 4);
    wsplit<<<dim3(VDIMc / 32, DMc / 32), 256>>>(Wv, bvw, VDIMc, DMc);
    wsplit<<<dim3(ADIMc / 32, DMc / 32), 256>>>(Wa, baw, ADIMc, DMc);
    wsplit<<<dim3(XDIM / 32, HIDc / 32), 256>>>(W1, b1w, XDIM, HIDc);

    // projections
    mma_gemm<false><<<dim3(DMc / 128, MROWS / 128), 256, GSM_TOTAL>>>(
        vh, vl, bvw, bv, nullptr, gv, VDIMc, DMc);
    mma_gemm<false><<<dim3(DMc / 128, MROWS / 128), 256, GSM_TOTAL>>>(
        ah, al, baw, ba, nullptr, ga, ADIMc, DMc);

    ln_kernel<<<MROWS, 256>>>(gv);
    ln_kernel<<<MROWS, 256>>>(ga);
    shiftctx_kernel<<<dim3(Tc, Bc), 256>>>(theta);
    xbuild_kernel<<<MROWS, 256>>>();

    // gate MLP with fused gelu + W2 reduction
    mma_gemm<true><<<dim3(HIDc / 128, MROWS / 128), 256, GSM_TOTAL>>>(
        xh, xl, b1w, b1, W2, gpart, XDIM, HIDc);

    final_kernel<<<MROWS, 256>>>(b2, out);
}